// round 5
// baseline (speedup 1.0000x reference)
#include <cuda_runtime.h>
#include <math.h>
#include <stdint.h>

// Problem dims
#define BB 128
#define TT 512
#define II 300
#define HH 256
#define G4 1024   // 4*H

// persist kernel geometry
#define CL 8          // CTAs per cluster
#define NCLUS 16      // clusters
#define PW 268        // W_s row stride (floats): 12 mod 32 -> bank-tiling rows
#define PH 264        // h row stride (floats): 8 mod 32
#define KOFF 132      // K-half offset inside a row (4 mod 32)

// Scratch (device globals — no allocations allowed)
__device__ float g_xp[(size_t)TT * BB * G4];   // [t][b][gate]  (256 MB)
__device__ float g_hf[BB * HH];                // forward-dir final hidden
__device__ float g_hb[BB * HH];                // backward-dir final hidden

__device__ __forceinline__ float fast_sigmoid(float v) {
    return 1.0f / (1.0f + __expf(-v));
}
__device__ __forceinline__ float fast_tanh(float v) {
    return __fdividef(2.0f, 1.0f + __expf(-2.0f * v)) - 1.0f;
}

// packed dual-fp32 FMA
__device__ __forceinline__ void fma2(float2& acc, float2 a, float2 b) {
    asm("fma.rn.f32x2 %0, %1, %2, %0;"
        : "+l"(reinterpret_cast<unsigned long long&>(acc))
        : "l"(reinterpret_cast<unsigned long long&>(a)),
          "l"(reinterpret_cast<unsigned long long&>(b)));
}

__device__ __forceinline__ void st_remote_f32(uint32_t saddr, uint32_t trank, float v) {
    uint32_t ra;
    asm volatile("mapa.shared::cluster.u32 %0, %1, %2;" : "=r"(ra) : "r"(saddr), "r"(trank));
    asm volatile("st.shared::cluster.f32 [%0], %1;" :: "r"(ra), "f"(v) : "memory");
}

// ---------------------------------------------------------------------------
// xp GEMM: xp[t][b][n] = sum_i x[b][t][i] * W_ih_f[n][i] + b_f[n]
// ---------------------------------------------------------------------------
__global__ void xp_gemm(const float* __restrict__ A,
                        const float* __restrict__ W,
                        const float* __restrict__ bias) {
    __shared__ float As[8][132];
    __shared__ float Bs[8][132];

    const int nt = blockIdx.x;          // 0..7
    const int mt = blockIdx.y;          // 0..511
    const int tid = threadIdx.x;        // 0..255
    const int tx = tid & 15;
    const int ty = tid >> 4;

    const int m0 = mt * 128;
    const int n0 = nt * 128;

    float2 acc2[4][8];
#pragma unroll
    for (int ip = 0; ip < 4; ip++)
#pragma unroll
        for (int j = 0; j < 8; j++) acc2[ip][j] = make_float2(0.f, 0.f);

    for (int k0 = 0; k0 < II; k0 += 8) {
#pragma unroll
        for (int e = tid; e < 1024; e += 256) {
            int r = e >> 3;
            int kk = e & 7;
            int k = k0 + kk;
            As[kk][r] = (k < II) ? A[(size_t)(m0 + r) * II + k] : 0.0f;
            Bs[kk][r] = (k < II) ? W[(size_t)(n0 + r) * II + k] : 0.0f;
        }
        __syncthreads();

#pragma unroll
        for (int kk = 0; kk < 8; kk++) {
            float4 a0 = *(const float4*)&As[kk][ty * 8];
            float4 a1 = *(const float4*)&As[kk][ty * 8 + 4];
            float4 b0 = *(const float4*)&Bs[kk][tx * 8];
            float4 b1 = *(const float4*)&Bs[kk][tx * 8 + 4];
            float2 ap[4] = { {a0.x, a0.y}, {a0.z, a0.w}, {a1.x, a1.y}, {a1.z, a1.w} };
            float bj[8] = { b0.x, b0.y, b0.z, b0.w, b1.x, b1.y, b1.z, b1.w };
#pragma unroll
            for (int j = 0; j < 8; j++) {
                float2 bb = make_float2(bj[j], bj[j]);
#pragma unroll
                for (int ip = 0; ip < 4; ip++) fma2(acc2[ip][j], ap[ip], bb);
            }
        }
        __syncthreads();
    }

#pragma unroll
    for (int i = 0; i < 8; i++) {
        int m = m0 + ty * 8 + i;
        int bidx = m >> 9;
        int t = m & 511;
        size_t base = ((size_t)t * BB + bidx) * G4;
#pragma unroll
        for (int j = 0; j < 8; j++) {
            int n = n0 + tx * 8 + j;
            float v = (i & 1) ? acc2[i >> 1][j].y : acc2[i >> 1][j].x;
            g_xp[base + n] = v + bias[n];
        }
    }
}

// ---------------------------------------------------------------------------
// Backward direction: only ONE step matters (h0=c0=0 on x[:, T-1]).
// ---------------------------------------------------------------------------
__global__ void bwd_last(const float* __restrict__ x,
                         const float* __restrict__ Wb,
                         const float* __restrict__ bb) {
    const int b = blockIdx.x;
    const int tid = threadIdx.x;        // 256
    __shared__ float xs[304];
    __shared__ float gs[G4];

    const float* xr = x + ((size_t)b * TT + (TT - 1)) * II;
    for (int i = tid; i < II; i += 256) xs[i] = xr[i];
    __syncthreads();

    const int wid = tid >> 5;
    const int lane = tid & 31;
    for (int r = wid; r < G4; r += 8) {
        float s = 0.0f;
        const float* wr = Wb + (size_t)r * II;
        for (int i = lane; i < II; i += 32) s += xs[i] * wr[i];
#pragma unroll
        for (int off = 16; off > 0; off >>= 1)
            s += __shfl_down_sync(0xffffffffu, s, off);
        if (lane == 0) gs[r] = s + bb[r];
    }
    __syncthreads();

    if (tid < HH) {
        float ig = 1.0f / (1.0f + expf(-gs[tid]));
        float gg = tanhf(gs[512 + tid]);
        float og = 1.0f / (1.0f + expf(-gs[768 + tid]));
        float c = ig * gg;
        g_hb[b * HH + tid] = og * tanhf(c);
    }
}

// ---------------------------------------------------------------------------
// Persistent forward recurrence, cluster version (16 clusters x 8 CTAs,
// 8 batches per cluster, CTA rank holds 128 W rows in smem forever).
// 256 threads: tid = kh*128 + w8*32 + lane; lane = du*4 + bq.
//   u  = w8*8 + du : hidden unit (this CTA's unit u -> global rank*32+u)
//   bq : batch quad -> batches bq and bq+4
//   kh : K half [kh*128, kh*128+128)
// Thread computes 4 gate rows x 2 batches x K-half fully in registers.
// K halves combined via an 8-float smem exchange (kh=1 -> kh=0).
// Gate threads (kh=0) keep c0,c1 in registers; scatter h via DSMEM to all
// 8 cluster CTAs; one barrier.cluster per step.
// Bank layout: W rows stride 268 (12 mod 32), K-half offset 132 (4 mod 32)
// -> each gate LDS.128 per warp = 8 distinct rows = 128B conflict-free.
// h rows stride 264 (8 mod 32) -> 4 distinct batches, conflict-free.
// ---------------------------------------------------------------------------
__global__ void __launch_bounds__(256, 1) __cluster_dims__(CL, 1, 1)
lstm_persist(const float* __restrict__ Whh) {
    extern __shared__ float sm[];
    float* W_s = sm;                       // [128][PW]
    float* h_s = sm + 128 * PW;            // [2][8][PH]
    float* ex  = h_s + 2 * 8 * PH;         // [128][12]

    const int tid = threadIdx.x;
    uint32_t rank;
    asm("mov.u32 %0, %%cluster_ctarank;" : "=r"(rank));
    const int cid = blockIdx.x >> 3;

    // ---- load W slice once. local row lr = g*32+u -> global row g*256 + rank*32 + u
    for (int idx = tid; idx < 128 * 64; idx += 256) {
        int lr = idx >> 6;
        int k4 = idx & 63;
        int grow = (lr >> 5) * HH + (int)rank * 32 + (lr & 31);
        float4 v = *(const float4*)&Whh[(size_t)grow * HH + k4 * 4];
        int off = k4 * 4 + ((k4 >= 32) ? 4 : 0);
        *(float4*)&W_s[lr * PW + off] = v;
    }
    // zero h buffer 0 (buffer 1 fully overwritten by the first exchange)
    for (int i = tid; i < 8 * PH; i += 256) h_s[i] = 0.0f;
    __syncthreads();
    // cluster-ready barrier before any remote store
    asm volatile("barrier.cluster.arrive.aligned;" ::: "memory");
    asm volatile("barrier.cluster.wait.aligned;" ::: "memory");

    const int kh = tid >> 7;
    const int lane = tid & 31;
    const int w8 = (tid >> 5) & 3;
    const int u = w8 * 8 + (lane >> 2);
    const int bq = lane & 3;
    const int p = tid & 127;
    const int b0 = bq, b1 = bq + 4;

    float c0 = 0.f, c1 = 0.f, h0v = 0.f, h1v = 0.f;

    const uint32_t h_sh_base = (uint32_t)__cvta_generic_to_shared(h_s);
    const int kglob = (int)rank * 32 + u;
    const int koff = kglob + ((kglob >= 128) ? 4 : 0);

    for (int t = 0; t < TT; t++) {
        const int cur = t & 1;

        // prefetch xp (gate threads only; consumed after mainloop)
        float xr[8];
        if (kh == 0) {
            size_t base = ((size_t)t * BB + cid * 8) * G4 + kglob;
#pragma unroll
            for (int g = 0; g < 4; g++) {
                xr[g]     = __ldg(&g_xp[base + (size_t)b0 * G4 + g * 256]);
                xr[4 + g] = __ldg(&g_xp[base + (size_t)b1 * G4 + g * 256]);
            }
        }

        // mainloop
        const float* hb = h_s + cur * 8 * PH + kh * KOFF;
        const float* wb = W_s + u * PW + kh * KOFF;
        float2 acc[4][2];
#pragma unroll
        for (int g = 0; g < 4; g++) {
            acc[g][0] = make_float2(0.f, 0.f);
            acc[g][1] = make_float2(0.f, 0.f);
        }
#pragma unroll
        for (int k4 = 0; k4 < 32; k4++) {
            float4 ha = *(const float4*)(hb + b0 * PH + k4 * 4);
            float4 hc = *(const float4*)(hb + b1 * PH + k4 * 4);
            float2 hal = make_float2(ha.x, ha.y), hah = make_float2(ha.z, ha.w);
            float2 hcl = make_float2(hc.x, hc.y), hch = make_float2(hc.z, hc.w);
#pragma unroll
            for (int g = 0; g < 4; g++) {
                float4 w = *(const float4*)(wb + g * 32 * PW + k4 * 4);
                float2 wl = make_float2(w.x, w.y), wh = make_float2(w.z, w.w);
                fma2(acc[g][0], wl, hal);
                fma2(acc[g][0], wh, hah);
                fma2(acc[g][1], wl, hcl);
                fma2(acc[g][1], wh, hch);
            }
        }

        float s[8];
#pragma unroll
        for (int g = 0; g < 4; g++) {
            s[g]     = acc[g][0].x + acc[g][0].y;
            s[4 + g] = acc[g][1].x + acc[g][1].y;
        }

        if (kh == 1) {
            *(float4*)&ex[p * 12]     = make_float4(s[0], s[1], s[2], s[3]);
            *(float4*)&ex[p * 12 + 4] = make_float4(s[4], s[5], s[6], s[7]);
        }
        __syncthreads();

        if (kh == 0) {
            float4 e0 = *(const float4*)&ex[p * 12];
            float4 e1 = *(const float4*)&ex[p * 12 + 4];
            float pi0 = s[0] + e0.x + xr[0];
            float pf0 = s[1] + e0.y + xr[1];
            float pg0 = s[2] + e0.z + xr[2];
            float po0 = s[3] + e0.w + xr[3];
            float pi1 = s[4] + e1.x + xr[4];
            float pf1 = s[5] + e1.y + xr[5];
            float pg1 = s[6] + e1.z + xr[6];
            float po1 = s[7] + e1.w + xr[7];

            c0 = fast_sigmoid(pf0) * c0 + fast_sigmoid(pi0) * fast_tanh(pg0);
            c1 = fast_sigmoid(pf1) * c1 + fast_sigmoid(pi1) * fast_tanh(pg1);
            h0v = fast_sigmoid(po0) * fast_tanh(c0);
            h1v = fast_sigmoid(po1) * fast_tanh(c1);

            uint32_t off0 = h_sh_base +
                (uint32_t)(((cur ^ 1) * 8 * PH + b0 * PH + koff) * 4);
            uint32_t off1 = h_sh_base +
                (uint32_t)(((cur ^ 1) * 8 * PH + b1 * PH + koff) * 4);
#pragma unroll
            for (int r = 0; r < CL; r++) {
                st_remote_f32(off0, (uint32_t)r, h0v);
                st_remote_f32(off1, (uint32_t)r, h1v);
            }
        }
        // step barrier: orders DSMEM writes (arrive=release, wait=acquire),
        // also acts as CTA-level sync for the ex buffer
        asm volatile("barrier.cluster.arrive.aligned;" ::: "memory");
        asm volatile("barrier.cluster.wait.aligned;" ::: "memory");
    }

    if (kh == 0) {
        g_hf[(cid * 8 + b0) * HH + kglob] = h0v;
        g_hf[(cid * 8 + b1) * HH + kglob] = h1v;
    }
}

// ---------------------------------------------------------------------------
// Final linear
// ---------------------------------------------------------------------------
__global__ void final_lin(const float* __restrict__ Wlin,
                          const float* __restrict__ blin,
                          float* __restrict__ out) {
    const int b = blockIdx.x;
    const int tid = threadIdx.x;  // 256
    __shared__ float s0[256];
    __shared__ float s1[256];

    float hf = g_hf[b * HH + tid];
    float hb = g_hb[b * HH + tid];
    s0[tid] = hf * Wlin[tid] + hb * Wlin[HH + tid];
    s1[tid] = hf * Wlin[512 + tid] + hb * Wlin[512 + HH + tid];
    __syncthreads();
    for (int off = 128; off > 0; off >>= 1) {
        if (tid < off) {
            s0[tid] += s0[tid + off];
            s1[tid] += s1[tid + off];
        }
        __syncthreads();
    }
    if (tid == 0) {
        out[b * 2 + 0] = s0[0] + blin[0];
        out[b * 2 + 1] = s1[0] + blin[1];
    }
}

// ---------------------------------------------------------------------------
extern "C" void kernel_launch(void* const* d_in, const int* in_sizes, int n_in,
                              void* d_out, int out_size) {
    const float* x      = (const float*)d_in[0];
    const float* W_ih_f = (const float*)d_in[1];
    const float* W_hh_f = (const float*)d_in[2];
    const float* b_f    = (const float*)d_in[3];
    const float* W_ih_b = (const float*)d_in[4];
    // d_in[5] = W_hh_b : unused (backward dir needs only its first step, h0=0)
    const float* b_b    = (const float*)d_in[6];
    const float* W_lin  = (const float*)d_in[7];
    const float* b_lin  = (const float*)d_in[8];
    float* out = (float*)d_out;

    const int smem_bytes = (128 * PW + 2 * 8 * PH + 128 * 12) * 4;  // 160256
    cudaFuncSetAttribute(lstm_persist,
                         cudaFuncAttributeMaxDynamicSharedMemorySize, smem_bytes);

    xp_gemm<<<dim3(8, 512), 256>>>(x, W_ih_f, b_f);
    bwd_last<<<BB, 256>>>(x, W_ih_b, b_b);
    lstm_persist<<<NCLUS * CL, 256, smem_bytes>>>(W_hh_f);
    final_lin<<<BB, 256>>>(W_lin, b_lin, out);
}